// round 1
// baseline (speedup 1.0000x reference)
#include <cuda_runtime.h>
#include <math.h>

#define N_NODES 100000
#define N_EDGES 3200000
#define D_IN    512
#define D_OUT   256

// Scratch (no cudaMalloc allowed): 100000*256*4 = 102.4 MB
__device__ float g_presup[(size_t)N_NODES * D_OUT];
__device__ float g_colsum[D_OUT];

// ---------------------------------------------------------------------------
// 1) GEMM: pre_sup[M,256] = x[M,512] @ W[512,256]   (fp32, smem-tiled)
// ---------------------------------------------------------------------------
#define BM 128
#define BN 64
#define BK 16

__global__ __launch_bounds__(256) void gemm_kernel(const float* __restrict__ A,
                                                   const float* __restrict__ W) {
    __shared__ float As[BM][BK];
    __shared__ float Bs[BK][BN];

    const int tid = threadIdx.x;
    const int tx = tid & 15;       // 0..15 -> N direction (4 cols each)
    const int ty = tid >> 4;       // 0..15 -> M direction (8 rows each)
    const int m0 = blockIdx.y * BM;
    const int n0 = blockIdx.x * BN;

    float acc[8][4];
#pragma unroll
    for (int i = 0; i < 8; i++)
#pragma unroll
        for (int j = 0; j < 4; j++) acc[i][j] = 0.f;

    for (int k0 = 0; k0 < D_IN; k0 += BK) {
        // Load A tile: 128x16 floats = 512 float4, 2 per thread
#pragma unroll
        for (int l = 0; l < 2; l++) {
            int idx = tid + l * 256;
            int row = idx >> 2;          // 0..127
            int c4  = idx & 3;           // 0..3
            float4 v = make_float4(0.f, 0.f, 0.f, 0.f);
            int m = m0 + row;
            if (m < N_NODES)
                v = *(const float4*)(A + (size_t)m * D_IN + k0 + c4 * 4);
            *(float4*)(&As[row][c4 * 4]) = v;
        }
        // Load B tile: 16x64 floats = 256 float4, 1 per thread
        {
            int row = tid >> 4;          // 0..15
            int c4  = tid & 15;          // 0..15
            float4 v = *(const float4*)(W + (size_t)(k0 + row) * D_OUT + n0 + c4 * 4);
            *(float4*)(&Bs[row][c4 * 4]) = v;
        }
        __syncthreads();

#pragma unroll
        for (int k = 0; k < BK; k++) {
            float bf[4];
#pragma unroll
            for (int j = 0; j < 4; j++) bf[j] = Bs[k][tx * 4 + j];
#pragma unroll
            for (int i = 0; i < 8; i++) {
                float a = As[ty * 8 + i][k];
#pragma unroll
                for (int j = 0; j < 4; j++) acc[i][j] = fmaf(a, bf[j], acc[i][j]);
            }
        }
        __syncthreads();
    }

#pragma unroll
    for (int i = 0; i < 8; i++) {
        int m = m0 + ty * 8 + i;
        if (m < N_NODES) {
            *(float4*)(g_presup + (size_t)m * D_OUT + n0 + tx * 4) =
                make_float4(acc[i][0], acc[i][1], acc[i][2], acc[i][3]);
        }
    }
}

// ---------------------------------------------------------------------------
// 2) SpMM scatter: out[row[e]] += vals[e] * pre_sup[col[e]]   (one warp/edge)
// ---------------------------------------------------------------------------
__global__ __launch_bounds__(256) void spmm_kernel(const int* __restrict__ erow,
                                                   const int* __restrict__ ecol,
                                                   const float* __restrict__ evals,
                                                   float* __restrict__ out) {
    const int lane = threadIdx.x & 31;
    const int gw = (blockIdx.x * blockDim.x + threadIdx.x) >> 5;
    const int nw = (gridDim.x * blockDim.x) >> 5;

    for (int e = gw; e < N_EDGES; e += nw) {
        const int   r = __ldg(erow + e);
        const int   c = __ldg(ecol + e);
        const float v = __ldg(evals + e);
        const float4* src = (const float4*)(g_presup + (size_t)c * D_OUT);
        float* dst = out + (size_t)r * D_OUT;
#pragma unroll
        for (int j = 0; j < 2; j++) {
            float4 p = __ldg(src + lane + j * 32);
            float* d = dst + (size_t)(lane + j * 32) * 4;
            asm volatile(
                "red.global.add.v4.f32 [%0], {%1, %2, %3, %4};"
                :: "l"(d), "f"(p.x * v), "f"(p.y * v), "f"(p.z * v), "f"(p.w * v)
                : "memory");
        }
    }
}

// ---------------------------------------------------------------------------
// 3) Column sum-of-squares of (agg + b)
// ---------------------------------------------------------------------------
#define ROWS_PER_BLOCK 256
__global__ __launch_bounds__(256) void colsumsq_kernel(const float* __restrict__ out,
                                                       const float* __restrict__ b) {
    const int c = threadIdx.x;               // 256 threads = 256 columns
    const float bias = __ldg(b + c);
    const int r0 = blockIdx.x * ROWS_PER_BLOCK;
    const int r1 = min(r0 + ROWS_PER_BLOCK, N_NODES);
    float s = 0.f;
    for (int r = r0; r < r1; r++) {
        float v = out[(size_t)r * D_OUT + c] + bias;
        s = fmaf(v, v, s);
    }
    atomicAdd(&g_colsum[c], s);
}

__global__ void zero_colsum_kernel() { g_colsum[threadIdx.x] = 0.f; }

// ---------------------------------------------------------------------------
// 4) Finalize: out = softplus((agg + b) / max(col_norm, 1e-12))
// ---------------------------------------------------------------------------
__global__ __launch_bounds__(256) void finalize_kernel(float* __restrict__ out,
                                                       const float* __restrict__ b) {
    const int c = threadIdx.x;
    const float bias = __ldg(b + c);
    const float inv = 1.f / fmaxf(sqrtf(g_colsum[c]), 1e-12f);
    for (int r = blockIdx.x; r < N_NODES; r += gridDim.x) {
        float v = (out[(size_t)r * D_OUT + c] + bias) * inv;
        // numerically stable softplus = max(v,0) + log1p(exp(-|v|))
        out[(size_t)r * D_OUT + c] = fmaxf(v, 0.f) + log1pf(__expf(-fabsf(v)));
    }
}

// ---------------------------------------------------------------------------
extern "C" void kernel_launch(void* const* d_in, const int* in_sizes, int n_in,
                              void* d_out, int out_size) {
    const float* x     = (const float*)d_in[0];
    const int*   erow  = (const int*)  d_in[1];
    const int*   ecol  = (const int*)  d_in[2];
    const float* evals = (const float*)d_in[3];
    const float* W     = (const float*)d_in[4];
    const float* b     = (const float*)d_in[5];
    float* out = (float*)d_out;

    // Zero the accumulation target + column reduction buffer
    cudaMemsetAsync(out, 0, (size_t)N_NODES * D_OUT * sizeof(float), 0);
    zero_colsum_kernel<<<1, D_OUT>>>();

    // GEMM: pre_sup = x @ W
    dim3 ggrid(D_OUT / BN, (N_NODES + BM - 1) / BM);
    gemm_kernel<<<ggrid, 256>>>(x, W);

    // SpMM scatter with vector atomics
    spmm_kernel<<<2048, 256>>>(erow, ecol, evals, out);

    // Column L2 norm of (agg + b)
    colsumsq_kernel<<<(N_NODES + ROWS_PER_BLOCK - 1) / ROWS_PER_BLOCK, 256>>>(out, b);

    // Normalize + softplus
    finalize_kernel<<<4096, 256>>>(out, b);
}

// round 3
// speedup vs baseline: 1.1709x; 1.1709x over previous
#include <cuda_runtime.h>
#include <cuda_bf16.h>
#include <cstdint>
#include <math.h>

#define N_NODES 100000
#define N_EDGES 3200000
#define D_IN    512
#define D_OUT   256

// Scratch (no cudaMalloc allowed)
__device__ __align__(16) float g_presup[(size_t)N_NODES * D_OUT];   // 102.4 MB
__device__ float g_colsum[D_OUT];
__device__ __align__(16) __nv_bfloat16 g_Wth[(size_t)D_OUT * D_IN]; // W^T hi  [n][k]
__device__ __align__(16) __nv_bfloat16 g_Wtl[(size_t)D_OUT * D_IN]; // W^T lo  [n][k]

__device__ __forceinline__ uint32_t smem_u32(const void* p) {
    uint32_t a;
    asm("{ .reg .u64 t; cvta.to.shared.u64 t, %1; cvt.u32.u64 %0, t; }" : "=r"(a) : "l"(p));
    return a;
}
__device__ __forceinline__ uint32_t pack_bf2(__nv_bfloat16 a, __nv_bfloat16 b) {
    __nv_bfloat162 t = __halves2bfloat162(a, b);
    return *reinterpret_cast<uint32_t*>(&t);
}
__device__ __forceinline__ void ldmatrix_x4(uint32_t* r, uint32_t addr) {
    asm volatile("ldmatrix.sync.aligned.m8n8.x4.shared.b16 {%0,%1,%2,%3}, [%4];"
                 : "=r"(r[0]), "=r"(r[1]), "=r"(r[2]), "=r"(r[3]) : "r"(addr));
}
__device__ __forceinline__ void mma_bf16(float* d, const uint32_t* a, const uint32_t* b) {
    asm volatile(
        "mma.sync.aligned.m16n8k16.row.col.f32.bf16.bf16.f32 "
        "{%0,%1,%2,%3}, {%4,%5,%6,%7}, {%8,%9}, {%0,%1,%2,%3};"
        : "+f"(d[0]), "+f"(d[1]), "+f"(d[2]), "+f"(d[3])
        : "r"(a[0]), "r"(a[1]), "r"(a[2]), "r"(a[3]), "r"(b[0]), "r"(b[1]));
}

// ===========================================================================
// 0) W transpose + hi/lo bf16 split:  g_Wt{h,l}[n][k] = split(W[k][n])
// ===========================================================================
__global__ __launch_bounds__(256) void conv_w_kernel(const float* __restrict__ W) {
    int idx = blockIdx.x * 256 + threadIdx.x;       // over 512*256
    if (idx >= D_IN * D_OUT) return;
    int k = idx / D_OUT, n = idx % D_OUT;
    float v = W[idx];
    __nv_bfloat16 h = __float2bfloat16_rn(v);
    __nv_bfloat16 l = __float2bfloat16_rn(v - __bfloat162float(h));
    g_Wth[(size_t)n * D_IN + k] = h;
    g_Wtl[(size_t)n * D_IN + k] = l;
}

// ===========================================================================
// 1) GEMM: pre_sup = x @ W  via mma.sync bf16 hi/lo, fp32 accum
//    CTA tile 128x128x32; 8 warps (2M x 4N); warp tile 64x32
// ===========================================================================
#define BM 128
#define BN 128
#define BK 32
#define ROW_B 80           // padded row stride in bytes (32 bf16 = 64B data + 16 pad)
#define SA_HI 0
#define SA_LO 10240
#define SB_HI 20480
#define SB_LO 30720

__global__ __launch_bounds__(256, 1) void gemm_tc_kernel(const float* __restrict__ x) {
    __shared__ __align__(16) char smem[40960];
    const uint32_t sbase = smem_u32(smem);

    const int tid = threadIdx.x;
    const int wid = tid >> 5;
    const int lane = tid & 31;
    const int m0 = blockIdx.x * BM;
    const int n0 = blockIdx.y * BN;
    const int warp_m = (wid & 1) * 64;       // 0 or 64
    const int warp_n = (wid >> 1) * 32;      // 0,32,64,96

    float acc[4][4][4];
#pragma unroll
    for (int i = 0; i < 4; i++)
#pragma unroll
        for (int j = 0; j < 4; j++)
#pragma unroll
            for (int t = 0; t < 4; t++) acc[i][j][t] = 0.f;

    // per-lane ldmatrix base addresses (k-offset/tile offsets added in loop)
    const uint32_t aAddr = sbase + SA_HI +
        (uint32_t)((warp_m + (lane & 15)) * ROW_B + ((lane >> 4) << 4));
    const uint32_t bAddr = sbase + SB_HI +
        (uint32_t)((warp_n + (lane & 7)) * ROW_B + ((lane >> 3) << 4));

    for (int kc = 0; kc < D_IN / BK; kc++) {
        const int k0 = kc * BK;
        // ---- A tile: 128 rows x 32 fp32 -> bf16 hi/lo. 1024 float4, 4/thread
#pragma unroll
        for (int i = 0; i < 4; i++) {
            int idx = tid + i * 256;
            int row = idx >> 3;            // 8 float4 per 32-float row
            int f4  = idx & 7;
            int m = m0 + row;
            float4 a = make_float4(0.f, 0.f, 0.f, 0.f);
            if (m < N_NODES)
                a = *(const float4*)(x + (size_t)m * D_IN + k0 + f4 * 4);
            __nv_bfloat16 h0 = __float2bfloat16_rn(a.x), h1 = __float2bfloat16_rn(a.y);
            __nv_bfloat16 h2 = __float2bfloat16_rn(a.z), h3 = __float2bfloat16_rn(a.w);
            __nv_bfloat16 l0 = __float2bfloat16_rn(a.x - __bfloat162float(h0));
            __nv_bfloat16 l1 = __float2bfloat16_rn(a.y - __bfloat162float(h1));
            __nv_bfloat16 l2 = __float2bfloat16_rn(a.z - __bfloat162float(h2));
            __nv_bfloat16 l3 = __float2bfloat16_rn(a.w - __bfloat162float(h3));
            int off = row * ROW_B + f4 * 8;
            *(uint2*)(smem + SA_HI + off) = make_uint2(pack_bf2(h0, h1), pack_bf2(h2, h3));
            *(uint2*)(smem + SA_LO + off) = make_uint2(pack_bf2(l0, l1), pack_bf2(l2, l3));
        }
        // ---- B tiles: 128 n-rows x 32 k bf16 each (hi, lo). 1024 uint4, 4/thread
#pragma unroll
        for (int i = 0; i < 4; i++) {
            int idx = tid + i * 256;       // 0..1023; <512 hi, >=512 lo
            int sub = idx & 511;
            int row = sub >> 2;            // 4 uint4 per 32-bf16 row
            int ch  = sub & 3;
            int off = row * ROW_B + ch * 16;
            if (idx < 512)
                *(uint4*)(smem + SB_HI + off) =
                    *(const uint4*)(g_Wth + (size_t)(n0 + row) * D_IN + k0 + ch * 8);
            else
                *(uint4*)(smem + SB_LO + off) =
                    *(const uint4*)(g_Wtl + (size_t)(n0 + row) * D_IN + k0 + ch * 8);
        }
        __syncthreads();

        // ---- B fragments for both k16 steps (x4: r0,r1=step0; r2,r3=step1)
        uint32_t bh[4][4], bl[4][4];
#pragma unroll
        for (int nt = 0; nt < 4; nt++) {
            ldmatrix_x4(bh[nt], bAddr + nt * 8 * ROW_B);
            ldmatrix_x4(bl[nt], bAddr + nt * 8 * ROW_B + (SB_LO - SB_HI));
        }
#pragma unroll
        for (int ks = 0; ks < 2; ks++) {
            uint32_t ah[4][4], al[4][4];
#pragma unroll
            for (int mt = 0; mt < 4; mt++) {
                ldmatrix_x4(ah[mt], aAddr + mt * 16 * ROW_B + ks * 32);
                ldmatrix_x4(al[mt], aAddr + mt * 16 * ROW_B + ks * 32 + (SA_LO - SA_HI));
            }
#pragma unroll
            for (int mt = 0; mt < 4; mt++) {
#pragma unroll
                for (int nt = 0; nt < 4; nt++) {
                    uint32_t bhp[2] = {bh[nt][ks * 2], bh[nt][ks * 2 + 1]};
                    uint32_t blp[2] = {bl[nt][ks * 2], bl[nt][ks * 2 + 1]};
                    mma_bf16(acc[mt][nt], ah[mt], bhp);
                    mma_bf16(acc[mt][nt], ah[mt], blp);
                    mma_bf16(acc[mt][nt], al[mt], bhp);
                }
            }
        }
        __syncthreads();
    }

    // ---- Epilogue: acc -> g_presup
    const int mrow = m0 + warp_m + (lane >> 2);
    const int ncol = n0 + warp_n + (lane & 3) * 2;
#pragma unroll
    for (int mt = 0; mt < 4; mt++) {
#pragma unroll
        for (int nt = 0; nt < 4; nt++) {
            int m = mrow + mt * 16;
            int n = ncol + nt * 8;
            if (m < N_NODES)
                *(float2*)(g_presup + (size_t)m * D_OUT + n) =
                    make_float2(acc[mt][nt][0], acc[mt][nt][1]);
            if (m + 8 < N_NODES)
                *(float2*)(g_presup + (size_t)(m + 8) * D_OUT + n) =
                    make_float2(acc[mt][nt][2], acc[mt][nt][3]);
        }
    }
}

// ===========================================================================
// 2) SpMM scatter: out[row[e]] += vals[e] * pre_sup[col[e]]   (one warp/edge)
// ===========================================================================
__global__ __launch_bounds__(256) void spmm_kernel(const int* __restrict__ erow,
                                                   const int* __restrict__ ecol,
                                                   const float* __restrict__ evals,
                                                   float* __restrict__ out) {
    const int lane = threadIdx.x & 31;
    const int gw = (blockIdx.x * blockDim.x + threadIdx.x) >> 5;
    const int nw = (gridDim.x * blockDim.x) >> 5;

    for (int e = gw; e < N_EDGES; e += nw) {
        const int   r = __ldg(erow + e);
        const int   c = __ldg(ecol + e);
        const float v = __ldg(evals + e);
        const float4* src = (const float4*)(g_presup + (size_t)c * D_OUT);
        float* dst = out + (size_t)r * D_OUT;
#pragma unroll
        for (int j = 0; j < 2; j++) {
            float4 p = __ldg(src + lane + j * 32);
            float* d = dst + (size_t)(lane + j * 32) * 4;
            asm volatile(
                "red.global.add.v4.f32 [%0], {%1, %2, %3, %4};"
                :: "l"(d), "f"(p.x * v), "f"(p.y * v), "f"(p.z * v), "f"(p.w * v)
                : "memory");
        }
    }
}

// ===========================================================================
// 3) Column sum-of-squares of (agg + b)
// ===========================================================================
#define ROWS_PER_BLOCK 256
__global__ __launch_bounds__(256) void colsumsq_kernel(const float* __restrict__ out,
                                                       const float* __restrict__ b) {
    const int c = threadIdx.x;
    const float bias = __ldg(b + c);
    const int r0 = blockIdx.x * ROWS_PER_BLOCK;
    const int r1 = min(r0 + ROWS_PER_BLOCK, N_NODES);
    float s = 0.f;
    for (int r = r0; r < r1; r++) {
        float v = out[(size_t)r * D_OUT + c] + bias;
        s = fmaf(v, v, s);
    }
    atomicAdd(&g_colsum[c], s);
}

__global__ void zero_colsum_kernel() { g_colsum[threadIdx.x] = 0.f; }

// ===========================================================================
// 4) Finalize: out = softplus((agg + b) / max(col_norm, 1e-12))
// ===========================================================================
__global__ __launch_bounds__(256) void finalize_kernel(float* __restrict__ out,
                                                       const float* __restrict__ b) {
    const int c = threadIdx.x;
    const float bias = __ldg(b + c);
    const float inv = 1.f / fmaxf(sqrtf(g_colsum[c]), 1e-12f);
    for (int r = blockIdx.x; r < N_NODES; r += gridDim.x) {
        float v = (out[(size_t)r * D_OUT + c] + bias) * inv;
        out[(size_t)r * D_OUT + c] = fmaxf(v, 0.f) + log1pf(__expf(-fabsf(v)));
    }
}

// ===========================================================================
extern "C" void kernel_launch(void* const* d_in, const int* in_sizes, int n_in,
                              void* d_out, int out_size) {
    const float* x     = (const float*)d_in[0];
    const int*   erow  = (const int*)  d_in[1];
    const int*   ecol  = (const int*)  d_in[2];
    const float* evals = (const float*)d_in[3];
    const float* W     = (const float*)d_in[4];
    const float* b     = (const float*)d_in[5];
    float* out = (float*)d_out;

    cudaMemsetAsync(out, 0, (size_t)N_NODES * D_OUT * sizeof(float), 0);
    zero_colsum_kernel<<<1, D_OUT>>>();

    conv_w_kernel<<<(D_IN * D_OUT + 255) / 256, 256>>>(W);

    dim3 ggrid((N_NODES + BM - 1) / BM, D_OUT / BN);
    gemm_tc_kernel<<<ggrid, 256>>>(x);

    spmm_kernel<<<2048, 256>>>(erow, ecol, evals, out);

    colsumsq_kernel<<<(N_NODES + ROWS_PER_BLOCK - 1) / ROWS_PER_BLOCK, 256>>>(out, b);

    finalize_kernel<<<4096, 256>>>(out, b);
}

// round 4
// speedup vs baseline: 2.0474x; 1.7486x over previous
#include <cuda_runtime.h>
#include <cuda_bf16.h>
#include <cstdint>
#include <math.h>

#define N_NODES 100000
#define N_EDGES 3200000
#define D_IN    512
#define D_OUT   256
#define NB1     ((N_NODES + 1023) / 1024)   // 98 scan blocks

// Scratch (no cudaMalloc allowed)
__device__ __align__(16) float g_presup[(size_t)N_NODES * D_OUT];   // 102.4 MB
__device__ float g_colsum[D_OUT];
__device__ __align__(16) __nv_bfloat16 g_Wth[(size_t)D_OUT * D_IN]; // W^T hi  [n][k]
__device__ __align__(16) __nv_bfloat16 g_Wtl[(size_t)D_OUT * D_IN]; // W^T lo  [n][k]
// CSR binning scratch
__device__ int   g_counts[N_NODES];
__device__ int   g_rowptr[N_NODES + 1];
__device__ int   g_cursor[N_NODES];
__device__ int   g_blocksums[128];
__device__ __align__(16) int   g_csr_col[N_EDGES];
__device__ __align__(16) float g_csr_val[N_EDGES];

__device__ __forceinline__ uint32_t smem_u32(const void* p) {
    uint32_t a;
    asm("{ .reg .u64 t; cvta.to.shared.u64 t, %1; cvt.u32.u64 %0, t; }" : "=r"(a) : "l"(p));
    return a;
}
__device__ __forceinline__ uint32_t pack_bf2(__nv_bfloat16 a, __nv_bfloat16 b) {
    __nv_bfloat162 t = __halves2bfloat162(a, b);
    return *reinterpret_cast<uint32_t*>(&t);
}
__device__ __forceinline__ void ldmatrix_x4(uint32_t* r, uint32_t addr) {
    asm volatile("ldmatrix.sync.aligned.m8n8.x4.shared.b16 {%0,%1,%2,%3}, [%4];"
                 : "=r"(r[0]), "=r"(r[1]), "=r"(r[2]), "=r"(r[3]) : "r"(addr));
}
__device__ __forceinline__ void mma_bf16(float* d, const uint32_t* a, const uint32_t* b) {
    asm volatile(
        "mma.sync.aligned.m16n8k16.row.col.f32.bf16.bf16.f32 "
        "{%0,%1,%2,%3}, {%4,%5,%6,%7}, {%8,%9}, {%0,%1,%2,%3};"
        : "+f"(d[0]), "+f"(d[1]), "+f"(d[2]), "+f"(d[3])
        : "r"(a[0]), "r"(a[1]), "r"(a[2]), "r"(a[3]), "r"(b[0]), "r"(b[1]));
}

// ===========================================================================
// 0) W transpose + hi/lo bf16 split
// ===========================================================================
__global__ __launch_bounds__(256) void conv_w_kernel(const float* __restrict__ W) {
    int idx = blockIdx.x * 256 + threadIdx.x;
    if (idx >= D_IN * D_OUT) return;
    int k = idx / D_OUT, n = idx % D_OUT;
    float v = W[idx];
    __nv_bfloat16 h = __float2bfloat16_rn(v);
    __nv_bfloat16 l = __float2bfloat16_rn(v - __bfloat162float(h));
    g_Wth[(size_t)n * D_IN + k] = h;
    g_Wtl[(size_t)n * D_IN + k] = l;
}

// ===========================================================================
// 1) GEMM: pre_sup = x @ W  via mma.sync bf16 hi/lo, fp32 accum (unchanged)
// ===========================================================================
#define BM 128
#define BN 128
#define BK 32
#define ROW_B 80
#define SA_HI 0
#define SA_LO 10240
#define SB_HI 20480
#define SB_LO 30720

__global__ __launch_bounds__(256, 1) void gemm_tc_kernel(const float* __restrict__ x) {
    __shared__ __align__(16) char smem[40960];
    const uint32_t sbase = smem_u32(smem);

    const int tid = threadIdx.x;
    const int wid = tid >> 5;
    const int lane = tid & 31;
    const int m0 = blockIdx.x * BM;
    const int n0 = blockIdx.y * BN;
    const int warp_m = (wid & 1) * 64;
    const int warp_n = (wid >> 1) * 32;

    float acc[4][4][4];
#pragma unroll
    for (int i = 0; i < 4; i++)
#pragma unroll
        for (int j = 0; j < 4; j++)
#pragma unroll
            for (int t = 0; t < 4; t++) acc[i][j][t] = 0.f;

    const uint32_t aAddr = sbase + SA_HI +
        (uint32_t)((warp_m + (lane & 15)) * ROW_B + ((lane >> 4) << 4));
    const uint32_t bAddr = sbase + SB_HI +
        (uint32_t)((warp_n + (lane & 7)) * ROW_B + ((lane >> 3) << 4));

    for (int kc = 0; kc < D_IN / BK; kc++) {
        const int k0 = kc * BK;
#pragma unroll
        for (int i = 0; i < 4; i++) {
            int idx = tid + i * 256;
            int row = idx >> 3;
            int f4  = idx & 7;
            int m = m0 + row;
            float4 a = make_float4(0.f, 0.f, 0.f, 0.f);
            if (m < N_NODES)
                a = *(const float4*)(x + (size_t)m * D_IN + k0 + f4 * 4);
            __nv_bfloat16 h0 = __float2bfloat16_rn(a.x), h1 = __float2bfloat16_rn(a.y);
            __nv_bfloat16 h2 = __float2bfloat16_rn(a.z), h3 = __float2bfloat16_rn(a.w);
            __nv_bfloat16 l0 = __float2bfloat16_rn(a.x - __bfloat162float(h0));
            __nv_bfloat16 l1 = __float2bfloat16_rn(a.y - __bfloat162float(h1));
            __nv_bfloat16 l2 = __float2bfloat16_rn(a.z - __bfloat162float(h2));
            __nv_bfloat16 l3 = __float2bfloat16_rn(a.w - __bfloat162float(h3));
            int off = row * ROW_B + f4 * 8;
            *(uint2*)(smem + SA_HI + off) = make_uint2(pack_bf2(h0, h1), pack_bf2(h2, h3));
            *(uint2*)(smem + SA_LO + off) = make_uint2(pack_bf2(l0, l1), pack_bf2(l2, l3));
        }
#pragma unroll
        for (int i = 0; i < 4; i++) {
            int idx = tid + i * 256;
            int sub = idx & 511;
            int row = sub >> 2;
            int ch  = sub & 3;
            int off = row * ROW_B + ch * 16;
            if (idx < 512)
                *(uint4*)(smem + SB_HI + off) =
                    *(const uint4*)(g_Wth + (size_t)(n0 + row) * D_IN + k0 + ch * 8);
            else
                *(uint4*)(smem + SB_LO + off) =
                    *(const uint4*)(g_Wtl + (size_t)(n0 + row) * D_IN + k0 + ch * 8);
        }
        __syncthreads();

        uint32_t bh[4][4], bl[4][4];
#pragma unroll
        for (int nt = 0; nt < 4; nt++) {
            ldmatrix_x4(bh[nt], bAddr + nt * 8 * ROW_B);
            ldmatrix_x4(bl[nt], bAddr + nt * 8 * ROW_B + (SB_LO - SB_HI));
        }
#pragma unroll
        for (int ks = 0; ks < 2; ks++) {
            uint32_t ah[4][4], al[4][4];
#pragma unroll
            for (int mt = 0; mt < 4; mt++) {
                ldmatrix_x4(ah[mt], aAddr + mt * 16 * ROW_B + ks * 32);
                ldmatrix_x4(al[mt], aAddr + mt * 16 * ROW_B + ks * 32 + (SA_LO - SA_HI));
            }
#pragma unroll
            for (int mt = 0; mt < 4; mt++) {
#pragma unroll
                for (int nt = 0; nt < 4; nt++) {
                    uint32_t bhp[2] = {bh[nt][ks * 2], bh[nt][ks * 2 + 1]};
                    uint32_t blp[2] = {bl[nt][ks * 2], bl[nt][ks * 2 + 1]};
                    mma_bf16(acc[mt][nt], ah[mt], bhp);
                    mma_bf16(acc[mt][nt], ah[mt], blp);
                    mma_bf16(acc[mt][nt], al[mt], bhp);
                }
            }
        }
        __syncthreads();
    }

    const int mrow = m0 + warp_m + (lane >> 2);
    const int ncol = n0 + warp_n + (lane & 3) * 2;
#pragma unroll
    for (int mt = 0; mt < 4; mt++) {
#pragma unroll
        for (int nt = 0; nt < 4; nt++) {
            int m = mrow + mt * 16;
            int n = ncol + nt * 8;
            if (m < N_NODES)
                *(float2*)(g_presup + (size_t)m * D_OUT + n) =
                    make_float2(acc[mt][nt][0], acc[mt][nt][1]);
            if (m + 8 < N_NODES)
                *(float2*)(g_presup + (size_t)(m + 8) * D_OUT + n) =
                    make_float2(acc[mt][nt][2], acc[mt][nt][3]);
        }
    }
}

// ===========================================================================
// 2a) CSR binning: count -> scan -> scatter
// ===========================================================================
__global__ __launch_bounds__(1024) void zero_counts_kernel() {
    int i = blockIdx.x * 1024 + threadIdx.x;
    if (i < N_NODES) g_counts[i] = 0;
}

__global__ __launch_bounds__(256) void count_kernel(const int* __restrict__ erow) {
    int e = blockIdx.x * 256 + threadIdx.x;
    if (e < N_EDGES) atomicAdd(&g_counts[__ldg(erow + e)], 1);
}

__global__ __launch_bounds__(1024) void scan1_kernel() {
    const int tid = threadIdx.x, lane = tid & 31, wid = tid >> 5;
    const int i = blockIdx.x * 1024 + tid;
    int v = (i < N_NODES) ? g_counts[i] : 0;
    int inc = v;
#pragma unroll
    for (int d = 1; d < 32; d <<= 1) {
        int t = __shfl_up_sync(~0u, inc, d);
        if (lane >= d) inc += t;
    }
    __shared__ int ws[32];
    if (lane == 31) ws[wid] = inc;
    __syncthreads();
    if (wid == 0) {
        int w = ws[lane];
#pragma unroll
        for (int d = 1; d < 32; d <<= 1) {
            int t = __shfl_up_sync(~0u, w, d);
            if (lane >= d) w += t;
        }
        ws[lane] = w;
    }
    __syncthreads();
    int base = wid ? ws[wid - 1] : 0;
    if (i < N_NODES) g_rowptr[i] = base + inc - v;       // exclusive within block
    if (tid == 0) g_blocksums[blockIdx.x] = ws[31];      // block total
}

__global__ __launch_bounds__(128) void scan2_kernel() {
    __shared__ int s[128];
    const int tid = threadIdx.x;
    s[tid] = (tid < NB1) ? g_blocksums[tid] : 0;
    __syncthreads();
    for (int d = 1; d < 128; d <<= 1) {
        int t = (tid >= d) ? s[tid - d] : 0;
        __syncthreads();
        s[tid] += t;
        __syncthreads();
    }
    g_blocksums[tid] = (tid > 0) ? s[tid - 1] : 0;       // exclusive block offsets
}

__global__ __launch_bounds__(1024) void scan3_kernel() {
    int i = blockIdx.x * 1024 + threadIdx.x;
    if (i < N_NODES) {
        int rp = g_rowptr[i] + g_blocksums[blockIdx.x];
        g_rowptr[i] = rp;
        g_cursor[i] = rp;
    }
    if (i == 0) g_rowptr[N_NODES] = N_EDGES;
}

__global__ __launch_bounds__(256) void scatter_kernel(const int* __restrict__ erow,
                                                      const int* __restrict__ ecol,
                                                      const float* __restrict__ evals) {
    int e = blockIdx.x * 256 + threadIdx.x;
    if (e >= N_EDGES) return;
    int r = __ldg(erow + e);
    int p = atomicAdd(&g_cursor[r], 1);
    g_csr_col[p] = __ldg(ecol + e);
    g_csr_val[p] = __ldg(evals + e);
}

// ===========================================================================
// 2b) SpMM CSR: one warp per row, register accumulation, no atomics
// ===========================================================================
__global__ __launch_bounds__(256) void spmm_csr_kernel(float* __restrict__ out) {
    const int lane = threadIdx.x & 31;
    const int r = (blockIdx.x * 256 + threadIdx.x) >> 5;
    if (r >= N_NODES) return;
    const int beg = __ldg(g_rowptr + r);
    const int end = __ldg(g_rowptr + r + 1);

    float4 A0 = make_float4(0.f, 0.f, 0.f, 0.f);
    float4 A1 = make_float4(0.f, 0.f, 0.f, 0.f);
    const float4* base = (const float4*)g_presup;
    const int lo = lane * 2;                 // float4 index within row

    int e = beg;
    for (; e + 2 <= end; e += 2) {
        int   c0 = __ldg(g_csr_col + e);
        int   c1 = __ldg(g_csr_col + e + 1);
        float v0 = __ldg(g_csr_val + e);
        float v1 = __ldg(g_csr_val + e + 1);
        const float4* s0 = base + (size_t)c0 * (D_OUT / 4) + lo;
        const float4* s1 = base + (size_t)c1 * (D_OUT / 4) + lo;
        float4 p00 = __ldg(s0), p01 = __ldg(s0 + 1);
        float4 p10 = __ldg(s1), p11 = __ldg(s1 + 1);
        A0.x = fmaf(v0, p00.x, A0.x); A0.y = fmaf(v0, p00.y, A0.y);
        A0.z = fmaf(v0, p00.z, A0.z); A0.w = fmaf(v0, p00.w, A0.w);
        A1.x = fmaf(v0, p01.x, A1.x); A1.y = fmaf(v0, p01.y, A1.y);
        A1.z = fmaf(v0, p01.z, A1.z); A1.w = fmaf(v0, p01.w, A1.w);
        A0.x = fmaf(v1, p10.x, A0.x); A0.y = fmaf(v1, p10.y, A0.y);
        A0.z = fmaf(v1, p10.z, A0.z); A0.w = fmaf(v1, p10.w, A0.w);
        A1.x = fmaf(v1, p11.x, A1.x); A1.y = fmaf(v1, p11.y, A1.y);
        A1.z = fmaf(v1, p11.z, A1.z); A1.w = fmaf(v1, p11.w, A1.w);
    }
    if (e < end) {
        int   c0 = __ldg(g_csr_col + e);
        float v0 = __ldg(g_csr_val + e);
        const float4* s0 = base + (size_t)c0 * (D_OUT / 4) + lo;
        float4 p00 = __ldg(s0), p01 = __ldg(s0 + 1);
        A0.x = fmaf(v0, p00.x, A0.x); A0.y = fmaf(v0, p00.y, A0.y);
        A0.z = fmaf(v0, p00.z, A0.z); A0.w = fmaf(v0, p00.w, A0.w);
        A1.x = fmaf(v0, p01.x, A1.x); A1.y = fmaf(v0, p01.y, A1.y);
        A1.z = fmaf(v0, p01.z, A1.z); A1.w = fmaf(v0, p01.w, A1.w);
    }

    float4* dst = (float4*)(out + (size_t)r * D_OUT) + lo;
    dst[0] = A0;
    dst[1] = A1;
}

// ===========================================================================
// 3) Column sum-of-squares of (agg + b)
// ===========================================================================
#define ROWS_PER_BLOCK 256
__global__ __launch_bounds__(256) void colsumsq_kernel(const float* __restrict__ out,
                                                       const float* __restrict__ b) {
    const int c = threadIdx.x;
    const float bias = __ldg(b + c);
    const int r0 = blockIdx.x * ROWS_PER_BLOCK;
    const int r1 = min(r0 + ROWS_PER_BLOCK, N_NODES);
    float s = 0.f;
    for (int r = r0; r < r1; r++) {
        float v = out[(size_t)r * D_OUT + c] + bias;
        s = fmaf(v, v, s);
    }
    atomicAdd(&g_colsum[c], s);
}

__global__ void zero_colsum_kernel() { g_colsum[threadIdx.x] = 0.f; }

// ===========================================================================
// 4) Finalize: out = softplus((agg + b) / max(col_norm, 1e-12))
// ===========================================================================
__global__ __launch_bounds__(256) void finalize_kernel(float* __restrict__ out,
                                                       const float* __restrict__ b) {
    const int c = threadIdx.x;
    const float bias = __ldg(b + c);
    const float inv = 1.f / fmaxf(sqrtf(g_colsum[c]), 1e-12f);
    for (int r = blockIdx.x; r < N_NODES; r += gridDim.x) {
        float v = (out[(size_t)r * D_OUT + c] + bias) * inv;
        out[(size_t)r * D_OUT + c] = fmaxf(v, 0.f) + log1pf(__expf(-fabsf(v)));
    }
}

// ===========================================================================
extern "C" void kernel_launch(void* const* d_in, const int* in_sizes, int n_in,
                              void* d_out, int out_size) {
    const float* x     = (const float*)d_in[0];
    const int*   erow  = (const int*)  d_in[1];
    const int*   ecol  = (const int*)  d_in[2];
    const float* evals = (const float*)d_in[3];
    const float* W     = (const float*)d_in[4];
    const float* b     = (const float*)d_in[5];
    float* out = (float*)d_out;

    zero_colsum_kernel<<<1, D_OUT>>>();
    conv_w_kernel<<<(D_IN * D_OUT + 255) / 256, 256>>>(W);

    // CSR binning (independent of GEMM)
    zero_counts_kernel<<<NB1, 1024>>>();
    count_kernel<<<(N_EDGES + 255) / 256, 256>>>(erow);
    scan1_kernel<<<NB1, 1024>>>();
    scan2_kernel<<<1, 128>>>();
    scan3_kernel<<<NB1, 1024>>>();
    scatter_kernel<<<(N_EDGES + 255) / 256, 256>>>(erow, ecol, evals);

    // GEMM
    dim3 ggrid((N_NODES + BM - 1) / BM, D_OUT / BN);
    gemm_tc_kernel<<<ggrid, 256>>>(x);

    // SpMM (CSR, no atomics); writes every output row
    spmm_csr_kernel<<<(N_NODES * 32 + 255) / 256, 256>>>(out);

    colsumsq_kernel<<<(N_NODES + ROWS_PER_BLOCK - 1) / ROWS_PER_BLOCK, 256>>>(out, b);
    finalize_kernel<<<4096, 256>>>(out, b);
}

// round 5
// speedup vs baseline: 2.4685x; 1.2056x over previous
#include <cuda_runtime.h>
#include <cuda_bf16.h>
#include <cstdint>
#include <math.h>

#define N_NODES 100000
#define N_EDGES 3200000
#define D_IN    512
#define D_OUT   256
#define NB1     ((N_NODES + 1023) / 1024)   // 98 scan blocks

// Scratch (no cudaMalloc allowed)
__device__ __align__(16) float g_presup[(size_t)N_NODES * D_OUT];   // 102.4 MB
__device__ float g_colsum[D_OUT];
__device__ __align__(16) __nv_bfloat16 g_Wth[(size_t)D_OUT * D_IN]; // W^T hi  [n][k]
__device__ __align__(16) __nv_bfloat16 g_Wtl[(size_t)D_OUT * D_IN]; // W^T lo  [n][k]
// CSR binning scratch
__device__ int   g_counts[N_NODES];
__device__ int   g_rowptr[N_NODES + 1];
__device__ int   g_cursor[N_NODES];
__device__ int   g_blocksums[128];
__device__ __align__(16) int2 g_csr_pair[N_EDGES];   // (col, val bits)

__device__ __forceinline__ uint32_t smem_u32(const void* p) {
    uint32_t a;
    asm("{ .reg .u64 t; cvta.to.shared.u64 t, %1; cvt.u32.u64 %0, t; }" : "=r"(a) : "l"(p));
    return a;
}
__device__ __forceinline__ uint32_t pack_bf2(__nv_bfloat16 a, __nv_bfloat16 b) {
    __nv_bfloat162 t = __halves2bfloat162(a, b);
    return *reinterpret_cast<uint32_t*>(&t);
}
__device__ __forceinline__ void ldmatrix_x4(uint32_t* r, uint32_t addr) {
    asm volatile("ldmatrix.sync.aligned.m8n8.x4.shared.b16 {%0,%1,%2,%3}, [%4];"
                 : "=r"(r[0]), "=r"(r[1]), "=r"(r[2]), "=r"(r[3]) : "r"(addr));
}
__device__ __forceinline__ void mma_bf16(float* d, const uint32_t* a, const uint32_t* b) {
    asm volatile(
        "mma.sync.aligned.m16n8k16.row.col.f32.bf16.bf16.f32 "
        "{%0,%1,%2,%3}, {%4,%5,%6,%7}, {%8,%9}, {%0,%1,%2,%3};"
        : "+f"(d[0]), "+f"(d[1]), "+f"(d[2]), "+f"(d[3])
        : "r"(a[0]), "r"(a[1]), "r"(a[2]), "r"(a[3]), "r"(b[0]), "r"(b[1]));
}
__device__ __forceinline__ void cp_async16(uint32_t dst, const void* src) {
    asm volatile("cp.async.cg.shared.global [%0], [%1], 16;"
                 :: "r"(dst), "l"(__cvta_generic_to_global(src)) : "memory");
}
#define CP_COMMIT() asm volatile("cp.async.commit_group;" ::: "memory")

// ===========================================================================
// 0) W transpose + hi/lo bf16 split
// ===========================================================================
__global__ __launch_bounds__(256) void conv_w_kernel(const float* __restrict__ W) {
    int idx = blockIdx.x * 256 + threadIdx.x;
    if (idx >= D_IN * D_OUT) return;
    int k = idx / D_OUT, n = idx % D_OUT;
    float v = W[idx];
    __nv_bfloat16 h = __float2bfloat16_rn(v);
    __nv_bfloat16 l = __float2bfloat16_rn(v - __bfloat162float(h));
    g_Wth[(size_t)n * D_IN + k] = h;
    g_Wtl[(size_t)n * D_IN + k] = l;
}

// ===========================================================================
// 1) GEMM: pre_sup = x @ W via mma.sync bf16 hi/lo, 2-stage cp.async pipeline
// ===========================================================================
#define BM 128
#define BN 128
#define BK 32
#define NKC (D_IN / BK)     // 16 chunks
#define ROW_B 80
#define ST_A_HI 0
#define ST_A_LO 10240
#define ST_B_HI 20480
#define ST_B_LO 30720
#define STAGE_B 40960
#define SM_TOTAL (2 * STAGE_B)   // 81920

__global__ __launch_bounds__(256, 1) void gemm_tc_kernel(const float* __restrict__ x) {
    extern __shared__ __align__(16) char smem[];
    const uint32_t sbase = smem_u32(smem);

    const int tid = threadIdx.x;
    const int wid = tid >> 5;
    const int lane = tid & 31;
    const int n0 = blockIdx.x * BN;    // grid.x = 2 (adjacent blocks share m0 -> x L2 reuse)
    const int m0 = blockIdx.y * BM;
    const int warp_m = (wid & 1) * 64;
    const int warp_n = (wid >> 1) * 32;

    // A ldg mapping: idx = tid + i*256 -> row = idx>>3 (0..127), f4 = idx&7
    const int a_row = tid >> 3;
    const int a_f4  = tid & 7;
    // B cp.async mapping: idx = tid + i*256 (i<4); sub = idx&511; row = sub>>2; ch = sub&3
    float4 areg[4];

    float acc[4][4][4];
#pragma unroll
    for (int i = 0; i < 4; i++)
#pragma unroll
        for (int j = 0; j < 4; j++)
#pragma unroll
            for (int t = 0; t < 4; t++) acc[i][j][t] = 0.f;

    const uint32_t aLane = (uint32_t)((warp_m + (lane & 15)) * ROW_B + ((lane >> 4) << 4));
    const uint32_t bLane = (uint32_t)((warp_n + (lane & 7)) * ROW_B + ((lane >> 3) << 4));

    auto ldgA = [&](int kc) {
        const int k0 = kc * BK;
#pragma unroll
        for (int i = 0; i < 4; i++) {
            int row = a_row + i * 32;
            int m = m0 + row;
            areg[i] = make_float4(0.f, 0.f, 0.f, 0.f);
            if (m < N_NODES)
                areg[i] = *(const float4*)(x + (size_t)m * D_IN + k0 + a_f4 * 4);
        }
    };
    auto stsA = [&](int st) {
        char* sb = smem + st * STAGE_B;
#pragma unroll
        for (int i = 0; i < 4; i++) {
            float4 a = areg[i];
            int row = a_row + i * 32;
            __nv_bfloat16 h0 = __float2bfloat16_rn(a.x), h1 = __float2bfloat16_rn(a.y);
            __nv_bfloat16 h2 = __float2bfloat16_rn(a.z), h3 = __float2bfloat16_rn(a.w);
            __nv_bfloat16 l0 = __float2bfloat16_rn(a.x - __bfloat162float(h0));
            __nv_bfloat16 l1 = __float2bfloat16_rn(a.y - __bfloat162float(h1));
            __nv_bfloat16 l2 = __float2bfloat16_rn(a.z - __bfloat162float(h2));
            __nv_bfloat16 l3 = __float2bfloat16_rn(a.w - __bfloat162float(h3));
            int off = row * ROW_B + a_f4 * 8;
            *(uint2*)(sb + ST_A_HI + off) = make_uint2(pack_bf2(h0, h1), pack_bf2(h2, h3));
            *(uint2*)(sb + ST_A_LO + off) = make_uint2(pack_bf2(l0, l1), pack_bf2(l2, l3));
        }
    };
    auto cpB = [&](int kc, int st) {
        const int k0 = kc * BK;
        const uint32_t stb = sbase + st * STAGE_B;
#pragma unroll
        for (int i = 0; i < 4; i++) {
            int idx = tid + i * 256;
            int sub = idx & 511;
            int row = sub >> 2;
            int ch  = sub & 3;
            uint32_t off = (uint32_t)(row * ROW_B + ch * 16);
            if (idx < 512)
                cp_async16(stb + ST_B_HI + off, g_Wth + (size_t)(n0 + row) * D_IN + k0 + ch * 8);
            else
                cp_async16(stb + ST_B_LO + off, g_Wtl + (size_t)(n0 + row) * D_IN + k0 + ch * 8);
        }
        CP_COMMIT();
    };

    // ---- prologue
    ldgA(0);
    cpB(0, 0);
    stsA(0);
    ldgA(1);
    cpB(1, 1);
    asm volatile("cp.async.wait_group 1;" ::: "memory");
    __syncthreads();

    for (int kc = 0; kc < NKC; kc++) {
        const int cur = kc & 1;
        const uint32_t base = sbase + cur * STAGE_B;

        // ---- compute on stage cur
        uint32_t bh[4][4], bl[4][4];
#pragma unroll
        for (int nt = 0; nt < 4; nt++) {
            ldmatrix_x4(bh[nt], base + ST_B_HI + bLane + nt * 8 * ROW_B);
            ldmatrix_x4(bl[nt], base + ST_B_LO + bLane + nt * 8 * ROW_B);
        }
#pragma unroll
        for (int ks = 0; ks < 2; ks++) {
            uint32_t ah[4][4], al[4][4];
#pragma unroll
            for (int mt = 0; mt < 4; mt++) {
                ldmatrix_x4(ah[mt], base + ST_A_HI + aLane + mt * 16 * ROW_B + ks * 32);
                ldmatrix_x4(al[mt], base + ST_A_LO + aLane + mt * 16 * ROW_B + ks * 32);
            }
#pragma unroll
            for (int mt = 0; mt < 4; mt++) {
#pragma unroll
                for (int nt = 0; nt < 4; nt++) {
                    uint32_t bhp[2] = {bh[nt][ks * 2], bh[nt][ks * 2 + 1]};
                    uint32_t blp[2] = {bl[nt][ks * 2], bl[nt][ks * 2 + 1]};
                    mma_bf16(acc[mt][nt], ah[mt], bhp);
                    mma_bf16(acc[mt][nt], ah[mt], blp);
                    mma_bf16(acc[mt][nt], al[mt], bhp);
                }
            }
        }

        // ---- stage next chunk
        if (kc < NKC - 1) stsA(cur ^ 1);        // A(kc+1) from regs
        __syncthreads();                        // readers of cur done; sts visible
        if (kc < NKC - 2) {
            ldgA(kc + 2);
            cpB(kc + 2, cur);                   // reuse stage cur
        }
        if (kc < NKC - 1) {
            if (kc < NKC - 2)
                asm volatile("cp.async.wait_group 1;" ::: "memory");
            else
                asm volatile("cp.async.wait_group 0;" ::: "memory");
            __syncthreads();
        }
    }

    // ---- epilogue
    const int mrow = m0 + warp_m + (lane >> 2);
    const int ncol = n0 + warp_n + (lane & 3) * 2;
#pragma unroll
    for (int mt = 0; mt < 4; mt++) {
#pragma unroll
        for (int nt = 0; nt < 4; nt++) {
            int m = mrow + mt * 16;
            int n = ncol + nt * 8;
            if (m < N_NODES)
                *(float2*)(g_presup + (size_t)m * D_OUT + n) =
                    make_float2(acc[mt][nt][0], acc[mt][nt][1]);
            if (m + 8 < N_NODES)
                *(float2*)(g_presup + (size_t)(m + 8) * D_OUT + n) =
                    make_float2(acc[mt][nt][2], acc[mt][nt][3]);
        }
    }
}

// ===========================================================================
// 2a) CSR binning: count -> scan -> scatter
// ===========================================================================
__global__ __launch_bounds__(1024) void zero_counts_kernel() {
    int i = blockIdx.x * 1024 + threadIdx.x;
    if (i < N_NODES) g_counts[i] = 0;
}

__global__ __launch_bounds__(256) void count_kernel(const int* __restrict__ erow) {
    int e = blockIdx.x * 256 + threadIdx.x;
    if (e < N_EDGES) atomicAdd(&g_counts[__ldg(erow + e)], 1);
}

__global__ __launch_bounds__(1024) void scan1_kernel() {
    const int tid = threadIdx.x, lane = tid & 31, wid = tid >> 5;
    const int i = blockIdx.x * 1024 + tid;
    int v = (i < N_NODES) ? g_counts[i] : 0;
    int inc = v;
#pragma unroll
    for (int d = 1; d < 32; d <<= 1) {
        int t = __shfl_up_sync(~0u, inc, d);
        if (lane >= d) inc += t;
    }
    __shared__ int ws[32];
    if (lane == 31) ws[wid] = inc;
    __syncthreads();
    if (wid == 0) {
        int w = ws[lane];
#pragma unroll
        for (int d = 1; d < 32; d <<= 1) {
            int t = __shfl_up_sync(~0u, w, d);
            if (lane >= d) w += t;
        }
        ws[lane] = w;
    }
    __syncthreads();
    int base = wid ? ws[wid - 1] : 0;
    if (i < N_NODES) g_rowptr[i] = base + inc - v;
    if (tid == 0) g_blocksums[blockIdx.x] = ws[31];
}

__global__ __launch_bounds__(128) void scan2_kernel() {
    __shared__ int s[128];
    const int tid = threadIdx.x;
    s[tid] = (tid < NB1) ? g_blocksums[tid] : 0;
    __syncthreads();
    for (int d = 1; d < 128; d <<= 1) {
        int t = (tid >= d) ? s[tid - d] : 0;
        __syncthreads();
        s[tid] += t;
        __syncthreads();
    }
    g_blocksums[tid] = (tid > 0) ? s[tid - 1] : 0;
}

__global__ __launch_bounds__(1024) void scan3_kernel() {
    int i = blockIdx.x * 1024 + threadIdx.x;
    if (i < N_NODES) {
        int rp = g_rowptr[i] + g_blocksums[blockIdx.x];
        g_rowptr[i] = rp;
        g_cursor[i] = rp;
    }
    if (i == 0) g_rowptr[N_NODES] = N_EDGES;
}

__global__ __launch_bounds__(256) void scatter_kernel(const int* __restrict__ erow,
                                                      const int* __restrict__ ecol,
                                                      const float* __restrict__ evals) {
    int e = blockIdx.x * 256 + threadIdx.x;
    if (e >= N_EDGES) return;
    int r = __ldg(erow + e);
    int p = atomicAdd(&g_cursor[r], 1);
    g_csr_pair[p] = make_int2(__ldg(ecol + e), __float_as_int(__ldg(evals + e)));
}

// ===========================================================================
// 2b) SpMM CSR: one warp per row, register accumulation, no atomics
// ===========================================================================
__global__ __launch_bounds__(256) void spmm_csr_kernel(float* __restrict__ out) {
    const int lane = threadIdx.x & 31;
    const int r = (blockIdx.x * 256 + threadIdx.x) >> 5;
    if (r >= N_NODES) return;
    const int beg = __ldg(g_rowptr + r);
    const int end = __ldg(g_rowptr + r + 1);

    float4 A0 = make_float4(0.f, 0.f, 0.f, 0.f);
    float4 A1 = make_float4(0.f, 0.f, 0.f, 0.f);
    const float4* base = (const float4*)g_presup;
    const int lo = lane * 2;

    int e = beg;
    for (; e + 2 <= end; e += 2) {
        int2 pr0 = __ldg(g_csr_pair + e);
        int2 pr1 = __ldg(g_csr_pair + e + 1);
        float v0 = __int_as_float(pr0.y);
        float v1 = __int_as_float(pr1.y);
        const float4* s0 = base + (size_t)pr0.x * (D_OUT / 4) + lo;
        const float4* s1 = base + (size_t)pr1.x * (D_OUT / 4) + lo;
        float4 p00 = __ldg(s0), p01 = __ldg(s0 + 1);
        float4 p10 = __ldg(s1), p11 = __ldg(s1 + 1);
        A0.x = fmaf(v0, p00.x, A0.x); A0.y = fmaf(v0, p00.y, A0.y);
        A0.z = fmaf(v0, p00.z, A0.z); A0.w = fmaf(v0, p00.w, A0.w);
        A1.x = fmaf(v0, p01.x, A1.x); A1.y = fmaf(v0, p01.y, A1.y);
        A1.z = fmaf(v0, p01.z, A1.z); A1.w = fmaf(v0, p01.w, A1.w);
        A0.x = fmaf(v1, p10.x, A0.x); A0.y = fmaf(v1, p10.y, A0.y);
        A0.z = fmaf(v1, p10.z, A0.z); A0.w = fmaf(v1, p10.w, A0.w);
        A1.x = fmaf(v1, p11.x, A1.x); A1.y = fmaf(v1, p11.y, A1.y);
        A1.z = fmaf(v1, p11.z, A1.z); A1.w = fmaf(v1, p11.w, A1.w);
    }
    if (e < end) {
        int2 pr0 = __ldg(g_csr_pair + e);
        float v0 = __int_as_float(pr0.y);
        const float4* s0 = base + (size_t)pr0.x * (D_OUT / 4) + lo;
        float4 p00 = __ldg(s0), p01 = __ldg(s0 + 1);
        A0.x = fmaf(v0, p00.x, A0.x); A0.y = fmaf(v0, p00.y, A0.y);
        A0.z = fmaf(v0, p00.z, A0.z); A0.w = fmaf(v0, p00.w, A0.w);
        A1.x = fmaf(v0, p01.x, A1.x); A1.y = fmaf(v0, p01.y, A1.y);
        A1.z = fmaf(v0, p01.z, A1.z); A1.w = fmaf(v0, p01.w, A1.w);
    }

    float4* dst = (float4*)(out + (size_t)r * D_OUT) + lo;
    dst[0] = A0;
    dst[1] = A1;
}

// ===========================================================================
// 3) Column sum-of-squares of (agg + b)
// ===========================================================================
#define ROWS_PER_BLOCK 256
__global__ __launch_bounds__(256) void colsumsq_kernel(const float* __restrict__ out,
                                                       const float* __restrict__ b) {
    const int c = threadIdx.x;
    const float bias = __ldg(b + c);
    const int r0 = blockIdx.x * ROWS_PER_BLOCK;
    const int r1 = min(r0 + ROWS_PER_BLOCK, N_NODES);
    float s = 0.f;
    for (int r = r0; r < r1; r++) {
        float v = out[(size_t)r * D_OUT + c] + bias;
        s = fmaf(v, v, s);
    }
    atomicAdd(&g_colsum[c], s);
}

__global__ void zero_colsum_kernel() { g_colsum[threadIdx.x] = 0.f; }

// ===========================================================================
// 4) Finalize: out = softplus((agg + b) / max(col_norm, 1e-12))
// ===========================================================================
__global__ __launch_bounds__(256) void finalize_kernel(float* __restrict__ out,
                                                       const float* __restrict__ b) {
    const int c = threadIdx.x;
    const float bias = __ldg(b + c);
    const float inv = 1.f / fmaxf(sqrtf(g_colsum[c]), 1e-12f);
    for (int r = blockIdx.x; r < N_NODES; r += gridDim.x) {
        float v = (out[(size_t)r * D_OUT + c] + bias) * inv;
        out[(size_t)r * D_OUT + c] = fmaxf(v, 0.f) + log1pf(__expf(-fabsf(v)));
    }
}

// ===========================================================================
extern "C" void kernel_launch(void* const* d_in, const int* in_sizes, int n_in,
                              void* d_out, int out_size) {
    const float* x     = (const float*)d_in[0];
    const int*   erow  = (const int*)  d_in[1];
    const int*   ecol  = (const int*)  d_in[2];
    const float* evals = (const float*)d_in[3];
    const float* W     = (const float*)d_in[4];
    const float* b     = (const float*)d_in[5];
    float* out = (float*)d_out;

    cudaFuncSetAttribute(gemm_tc_kernel,
                         cudaFuncAttributeMaxDynamicSharedMemorySize, SM_TOTAL);

    zero_colsum_kernel<<<1, D_OUT>>>();
    conv_w_kernel<<<(D_IN * D_OUT + 255) / 256, 256>>>(W);

    // CSR binning (independent of GEMM)
    zero_counts_kernel<<<NB1, 1024>>>();
    count_kernel<<<(N_EDGES + 255) / 256, 256>>>(erow);
    scan1_kernel<<<NB1, 1024>>>();
    scan2_kernel<<<1, 128>>>();
    scan3_kernel<<<NB1, 1024>>>();
    scatter_kernel<<<(N_EDGES + 255) / 256, 256>>>(erow, ecol, evals);

    // GEMM (grid.x = N-blocks so both share the m-tile in L2)
    dim3 ggrid(D_OUT / BN, (N_NODES + BM - 1) / BM);
    gemm_tc_kernel<<<ggrid, 256, SM_TOTAL>>>(x);

    // SpMM (CSR, no atomics)
    spmm_csr_kernel<<<(N_NODES * 32 + 255) / 256, 256>>>(out);

    colsumsq_kernel<<<(N_NODES + ROWS_PER_BLOCK - 1) / ROWS_PER_BLOCK, 256>>>(out, b);
    finalize_kernel<<<4096, 256>>>(out, b);
}